// round 3
// baseline (speedup 1.0000x reference)
#include <cuda_runtime.h>
#include <math.h>

// sym_logm of B SPD 64x64 fp32 matrices.
// Kernel 1: one-sided Hestenes Jacobi, one warp per matrix. Each lane holds
//   FOUR HALF-COLUMNS (rows [32*half,32*half+32) of 4 columns); lanes g and
//   g+16 are the two halves. Brent-Luk tournament over 64 ring slots: 2 of 4
//   per-lane moves are intra-lane (free, fused into rotation writes), so only
//   64 floats cross lanes per round (half of the 2-full-column layout).
//   All rotation/dot math uses packed fma.rn.f32x2 / mul.rn.f32x2.
// Kernel 2: out[b] = sum_k w_k g_k g_k^T via scratch P,Q.

#define MAXB 8192
#define NMAT 64
typedef unsigned long long u64;

__device__ float g_P[(size_t)MAXB * NMAT * NMAT];
__device__ float g_Q[(size_t)MAXB * NMAT * NMAT];

__device__ __forceinline__ u64 pk(float lo, float hi) {
    u64 r; asm("mov.b64 %0,{%1,%2};" : "=l"(r) : "f"(lo), "f"(hi)); return r;
}
__device__ __forceinline__ void upk(u64 v, float& lo, float& hi) {
    asm("mov.b64 {%0,%1},%2;" : "=f"(lo), "=f"(hi) : "l"(v));
}
__device__ __forceinline__ u64 fma2_(u64 a, u64 b, u64 c) {
    u64 d; asm("fma.rn.f32x2 %0,%1,%2,%3;" : "=l"(d) : "l"(a), "l"(b), "l"(c)); return d;
}
__device__ __forceinline__ u64 mul2_(u64 a, u64 b) {
    u64 d; asm("mul.rn.f32x2 %0,%1,%2;" : "=l"(d) : "l"(a), "l"(b)); return d;
}

__global__ __launch_bounds__(128) void jacobi_half(const float* __restrict__ X, int B)
{
    const int warp = blockIdx.x * (blockDim.x >> 5) + (threadIdx.x >> 5);
    if (warp >= B) return;
    const int lane = threadIdx.x & 31;
    const int g    = lane & 15;          // ring group 0..15
    const int half = lane >> 4;          // 0: rows 0..31, 1: rows 32..63
    const unsigned FULL = 0xffffffffu;

    // Slot s of group g holds column (4g+s); lane keeps its half (32 floats = 16 u64).
    u64 S0[16], S1[16], S2[16], S3[16];
    {
        const float4* x4 = (const float4*)(X + (size_t)warp * 4096);
        #pragma unroll
        for (int r = 0; r < 8; ++r) {
            float4 v;
            v = x4[(4*g+0)*16 + half*8 + r]; S0[2*r] = pk(v.x, v.y); S0[2*r+1] = pk(v.z, v.w);
            v = x4[(4*g+1)*16 + half*8 + r]; S1[2*r] = pk(v.x, v.y); S1[2*r+1] = pk(v.z, v.w);
            v = x4[(4*g+2)*16 + half*8 + r]; S2[2*r] = pk(v.x, v.y); S2[2*r+1] = pk(v.z, v.w);
            v = x4[(4*g+3)*16 + half*8 + r]; S3[2*r] = pk(v.x, v.y); S3[2*r+1] = pk(v.z, v.w);
        }
    }

    // Column norms (lambda^2 for SPD), replicated bit-identically across halves.
    float n0, n1, n2, n3;
    {
        u64 a0 = 0, a1 = 0, a2 = 0, a3 = 0;
        #pragma unroll
        for (int j = 0; j < 16; ++j) {
            a0 = fma2_(S0[j], S0[j], a0); a1 = fma2_(S1[j], S1[j], a1);
            a2 = fma2_(S2[j], S2[j], a2); a3 = fma2_(S3[j], S3[j], a3);
        }
        float lo, hi, p;
        upk(a0, lo, hi); p = lo + hi; n0 = p + __shfl_xor_sync(FULL, p, 16);
        upk(a1, lo, hi); p = lo + hi; n1 = p + __shfl_xor_sync(FULL, p, 16);
        upk(a2, lo, hi); p = lo + hi; n2 = p + __shfl_xor_sync(FULL, p, 16);
        upk(a3, lo, hi); p = lo + hi; n3 = p + __shfl_xor_sync(FULL, p, 16);
    }

    for (int sweep = 0; sweep < 30; ++sweep) {
        int any = 0;
        #pragma unroll 1
        for (int r = 0; r < 63; ++r) {
            // Pairs this round: A=(S0,S2)  B=(S1,S3)  [top pos 2g(+1) with bottom pos 2g(+1)]
            u64 dA = 0, dB = 0;
            #pragma unroll
            for (int j = 0; j < 16; ++j) {
                dA = fma2_(S0[j], S2[j], dA);
                dB = fma2_(S1[j], S3[j], dB);
            }
            float lo, hi;
            upk(dA, lo, hi); float pA = lo + hi;
            upk(dB, lo, hi); float pB = lo + hi;
            float apqA = pA + __shfl_xor_sync(FULL, pA, 16);
            float apqB = pB + __shfl_xor_sync(FULL, pB, 16);

            float cA = 1.f, sA = 0.f, tA = 0.f;
            bool rotA = (apqA * apqA > 9e-14f * n0 * n2);
            if (rotA) {
                float th = 0.5f * (n2 - n0) / apqA;
                tA = copysignf(1.f, th) / (fabsf(th) + sqrtf(fmaf(th, th, 1.f)));
                cA = rsqrtf(fmaf(tA, tA, 1.f));
                sA = tA * cA;
            }
            float cB = 1.f, sB = 0.f, tB = 0.f;
            bool rotB = (apqB * apqB > 9e-14f * n1 * n3);
            if (rotB) {
                float th = 0.5f * (n3 - n1) / apqB;
                tB = copysignf(1.f, th) / (fabsf(th) + sqrtf(fmaf(th, th, 1.f)));
                cB = rsqrtf(fmaf(tB, tB, 1.f));
                sB = tB * cB;
            }
            any |= (int)(rotA | rotB);

            float m0 = fmaf(-tA, apqA, n0), m2 = fmaf(tA, apqA, n2);
            float m1 = fmaf(-tB, apqB, n1), m3 = fmaf(tB, apqB, n3);

            u64 cA2 = pk(cA, cA), sA2 = pk(sA, sA), nsA2 = pk(-sA, -sA);
            u64 cB2 = pk(cB, cB), sB2 = pk(sB, sB), nsB2 = pk(-sB, -sB);

            // Rotate, then Brent-Luk move fused into destination writes:
            //   S1_g <- rotA(S0_g)  (g>=1);  S1_0 <- rotA(S2_0)
            //   S0_g <- rotB'(S1_{g-1}) via shfl; S0_0 <- rotA(S0_0) (fixed)
            //   S2_g <- rotB(S3_g)
            //   S3_g <- rotA'(S2_{g+1}) via shfl; S3_15 <- rotB(S1_15)
            #pragma unroll
            for (int j = 0; j < 16; ++j) {
                u64 x  = S0[j], y  = S2[j];
                u64 r0 = fma2_(cA2, x,  mul2_(nsA2, y));
                u64 r2 = fma2_(sA2, x,  mul2_(cA2,  y));
                u64 xb = S1[j], yb = S3[j];
                u64 r1 = fma2_(cB2, xb, mul2_(nsB2, yb));
                u64 r3 = fma2_(sB2, xb, mul2_(cB2,  yb));
                u64 up = __shfl_sync(FULL, r1, lane - 1);  // r1 of group g-1 (same half)
                u64 dn = __shfl_sync(FULL, r2, lane + 1);  // r2 of group g+1 (same half)
                S0[j] = (g == 0)  ? r0 : up;
                S1[j] = (g == 0)  ? r2 : r0;
                S2[j] = r3;
                S3[j] = (g == 15) ? r1 : dn;
            }
            // norms travel with their columns (same permutation)
            {
                float upn = __shfl_sync(FULL, m1, lane - 1);
                float dnn = __shfl_sync(FULL, m2, lane + 1);
                n0 = (g == 0)  ? m0 : upn;
                n1 = (g == 0)  ? m2 : m0;
                n2 = m3;
                n3 = (g == 15) ? m1 : dnn;
            }
        }
        if (!__any_sync(FULL, any)) break;
    }

    // Exact norms -> weights w = log(lambda)/lambda^2 = 0.5*log(n)/n
    float e0, e1, e2, e3;
    {
        u64 a0 = 0, a1 = 0, a2 = 0, a3 = 0;
        #pragma unroll
        for (int j = 0; j < 16; ++j) {
            a0 = fma2_(S0[j], S0[j], a0); a1 = fma2_(S1[j], S1[j], a1);
            a2 = fma2_(S2[j], S2[j], a2); a3 = fma2_(S3[j], S3[j], a3);
        }
        float lo, hi, p;
        upk(a0, lo, hi); p = lo + hi; e0 = p + __shfl_xor_sync(FULL, p, 16);
        upk(a1, lo, hi); p = lo + hi; e1 = p + __shfl_xor_sync(FULL, p, 16);
        upk(a2, lo, hi); p = lo + hi; e2 = p + __shfl_xor_sync(FULL, p, 16);
        upk(a3, lo, hi); p = lo + hi; e3 = p + __shfl_xor_sync(FULL, p, 16);
    }
    float w0 = 0.5f * logf(fmaxf(e0, 1e-30f)) / e0;
    float w1 = 0.5f * logf(fmaxf(e1, 1e-30f)) / e1;
    float w2 = 0.5f * logf(fmaxf(e2, 1e-30f)) / e2;
    float w3 = 0.5f * logf(fmaxf(e3, 1e-30f)) / e3;
    u64 w02 = pk(w0, w0), w12 = pk(w1, w1), w22 = pk(w2, w2), w32 = pk(w3, w3);

    // Store P = columns, Q = w * columns. Layout [b][col][row], rows contiguous.
    u64* Pp = (u64*)(g_P + (size_t)warp * 4096);
    u64* Qp = (u64*)(g_Q + (size_t)warp * 4096);
    const int boff = half * 16;
    #pragma unroll
    for (int j = 0; j < 16; ++j) {
        Pp[(4*g+0)*32 + boff + j] = S0[j];  Qp[(4*g+0)*32 + boff + j] = mul2_(w02, S0[j]);
        Pp[(4*g+1)*32 + boff + j] = S1[j];  Qp[(4*g+1)*32 + boff + j] = mul2_(w12, S1[j]);
        Pp[(4*g+2)*32 + boff + j] = S2[j];  Qp[(4*g+2)*32 + boff + j] = mul2_(w22, S2[j]);
        Pp[(4*g+3)*32 + boff + j] = S3[j];  Qp[(4*g+3)*32 + boff + j] = mul2_(w32, S3[j]);
    }
}

// out[b][i][j] = sum_k P[b][k][i] * Q[b][k][j]
__global__ __launch_bounds__(256) void gram_epilogue(float* __restrict__ out, int B)
{
    __shared__ float Ps[NMAT * NMAT];
    __shared__ float Qs[NMAT * NMAT];
    const int b = blockIdx.x;
    const int tid = threadIdx.x;
    const float* Pb = g_P + (size_t)b * (NMAT * NMAT);
    const float* Qb = g_Q + (size_t)b * (NMAT * NMAT);

    #pragma unroll
    for (int i = tid; i < NMAT * NMAT; i += 256) {
        Ps[i] = Pb[i];
        Qs[i] = Qb[i];
    }
    __syncthreads();

    const int ti = tid >> 6;
    const int tj = tid & 63;
    float acc[16];
    #pragma unroll
    for (int r = 0; r < 16; ++r) acc[r] = 0.0f;

    #pragma unroll 4
    for (int k = 0; k < NMAT; ++k) {
        float qv = Qs[k * NMAT + tj];
        const float4* prow = (const float4*)&Ps[k * NMAT + ti * 16];
        #pragma unroll
        for (int r4 = 0; r4 < 4; ++r4) {
            float4 p = prow[r4];
            acc[4*r4+0] = fmaf(p.x, qv, acc[4*r4+0]);
            acc[4*r4+1] = fmaf(p.y, qv, acc[4*r4+1]);
            acc[4*r4+2] = fmaf(p.z, qv, acc[4*r4+2]);
            acc[4*r4+3] = fmaf(p.w, qv, acc[4*r4+3]);
        }
    }

    float* Ob = out + (size_t)b * (NMAT * NMAT);
    #pragma unroll
    for (int r = 0; r < 16; ++r)
        Ob[(ti * 16 + r) * NMAT + tj] = acc[r];
}

extern "C" void kernel_launch(void* const* d_in, const int* in_sizes, int n_in,
                              void* d_out, int out_size) {
    const float* X = (const float*)d_in[0];
    float* out = (float*)d_out;
    int B = in_sizes[0] / (NMAT * NMAT);
    if (B > MAXB) B = MAXB;
    int blocks = (B + 3) / 4;
    jacobi_half<<<blocks, 128>>>(X, B);
    gram_epilogue<<<B, 256>>>(out, B);
}

// round 4
// speedup vs baseline: 1.6192x; 1.6192x over previous
#include <cuda_runtime.h>
#include <math.h>

// sym_logm of B SPD 64x64 fp32 matrices.
// Kernel 1: one-sided Hestenes Jacobi, one warp per matrix, 2 columns per lane
//   (C0 = col L, C1 = col L+32), both register-resident as u64 (f32x2 pairs).
//   Sweep = Phase A (mm=1..31): XOR pairing (j, j^mm) within each slot; data
//   static, partner column fetched by shfl_xor, both sides compute identical
//   (c,s), each rotates its own column. Cross phase (k=0..31): slot-1 columns
//   ring-shift one lane per round so lower-upper pairs are lane-local.
// Kernel 2: out[b] = sum_k w_k g_k g_k^T via scratch P,Q (unchanged, 149us).

#define MAXB 8192
#define NMAT 64
#define FULLM 0xffffffffu
typedef unsigned long long u64;

__device__ float g_P[(size_t)MAXB * NMAT * NMAT];
__device__ float g_Q[(size_t)MAXB * NMAT * NMAT];

__device__ __forceinline__ u64 pk(float lo, float hi) {
    u64 r; asm("mov.b64 %0,{%1,%2};" : "=l"(r) : "f"(lo), "f"(hi)); return r;
}
__device__ __forceinline__ void upk(u64 v, float& lo, float& hi) {
    asm("mov.b64 {%0,%1},%2;" : "=f"(lo), "=f"(hi) : "l"(v));
}
__device__ __forceinline__ u64 fma2_(u64 a, u64 b, u64 c) {
    u64 d; asm("fma.rn.f32x2 %0,%1,%2,%3;" : "=l"(d) : "l"(a), "l"(b), "l"(c)); return d;
}
__device__ __forceinline__ u64 mul2_(u64 a, u64 b) {
    u64 d; asm("mul.rn.f32x2 %0,%1,%2;" : "=l"(d) : "l"(a), "l"(b)); return d;
}

// One pair-side of a Phase-A round: own column C (32 u64 = 64 rows), own norm n.
// Partner column is shfl_xor(mm) of C across the warp. amP: own column is the
// lower index of the pair. Returns 1 if any lane rotated.
__device__ __forceinline__ int sideA(u64* C, float& n, int mm, bool amP)
{
    u64 R[32];
    #pragma unroll
    for (int j = 0; j < 32; ++j) R[j] = __shfl_xor_sync(FULLM, C[j], mm);

    u64 a0 = 0, a1 = 0;
    #pragma unroll
    for (int j = 0; j < 32; j += 2) {
        a0 = fma2_(C[j],   R[j],   a0);
        a1 = fma2_(C[j+1], R[j+1], a1);
    }
    float l0, h0, l1, h1; upk(a0, l0, h0); upk(a1, l1, h1);
    float apq = (l0 + h0) + (l1 + h1);         // bit-identical on both partners
    float pn  = __shfl_xor_sync(FULLM, n, mm); // partner's norm (single source)

    bool rot = (apq * apq > 1e-12f * n * pn);
    int active = (int)__any_sync(FULLM, rot);
    if (active) {
        float c = 1.0f, se = 0.0f;
        if (rot) {
            float np = amP ? n  : pn;
            float nq = amP ? pn : n;
            float th = 0.5f * (nq - np) / apq;
            float t  = copysignf(1.0f, th) / (fabsf(th) + sqrtf(fmaf(th, th, 1.0f)));
            c = rsqrtf(fmaf(t, t, 1.0f));
            float s = t * c;
            se = amP ? -s : s;                 // p: c*own - s*other ; q: c*own + s*other
            n  = fmaf(amP ? -t : t, apq, n);
        }
        u64 c2 = pk(c, c), se2 = pk(se, se);
        #pragma unroll
        for (int j = 0; j < 32; ++j)
            C[j] = fma2_(c2, C[j], mul2_(se2, R[j]));   // exact no-op when c=1,se=0
    }
    return active;
}

__global__ __launch_bounds__(128, 1) void jacobi_xor(const float* __restrict__ X, int B)
{
    const int warp = blockIdx.x * (blockDim.x >> 5) + (threadIdx.x >> 5);
    if (warp >= B) return;
    const int lane = threadIdx.x & 31;

    // C0 = column lane, C1 = column lane+32 (X symmetric: column c == row c).
    u64 C0[32], C1[32];
    {
        const float4* x4 = (const float4*)(X + (size_t)warp * 4096);
        #pragma unroll
        for (int r = 0; r < 16; ++r) {
            float4 v = x4[lane * 16 + r];
            C0[2*r]   = pk(v.x, v.y); C0[2*r+1] = pk(v.z, v.w);
            float4 w = x4[(lane + 32) * 16 + r];
            C1[2*r]   = pk(w.x, w.y); C1[2*r+1] = pk(w.z, w.w);
        }
    }

    float n0, n1;
    {
        u64 a0 = 0, a1 = 0;
        #pragma unroll
        for (int j = 0; j < 32; ++j) { a0 = fma2_(C0[j], C0[j], a0); a1 = fma2_(C1[j], C1[j], a1); }
        float lo, hi; upk(a0, lo, hi); n0 = lo + hi; upk(a1, lo, hi); n1 = lo + hi;
    }

    for (int sweep = 0; sweep < 28; ++sweep) {
        int any = 0;

        // ---- Phase A: XOR pairs within each slot (lower-lower, upper-upper) ----
        #pragma unroll 1
        for (int mm = 1; mm < 32; ++mm) {
            bool amP = (lane < (lane ^ mm));
            any |= sideA(C0, n0, mm, amP);
            any |= sideA(C1, n1, mm, amP);
        }

        // ---- Cross phase: lane-local pairs (C0, C1); ring-shift C1 each round ----
        #pragma unroll 1
        for (int k = 0; k < 32; ++k) {
            u64 a0 = 0, a1 = 0;
            #pragma unroll
            for (int j = 0; j < 32; j += 2) {
                a0 = fma2_(C0[j],   C1[j],   a0);
                a1 = fma2_(C0[j+1], C1[j+1], a1);
            }
            float l0, h0, l1, h1; upk(a0, l0, h0); upk(a1, l1, h1);
            float apq = (l0 + h0) + (l1 + h1);

            bool rot = (apq * apq > 1e-12f * n0 * n1);
            if (__any_sync(FULLM, rot)) {
                float c = 1.0f, s = 0.0f;
                if (rot) {
                    float th = 0.5f * (n1 - n0) / apq;   // C0 is always p (lower index)
                    float t  = copysignf(1.0f, th) / (fabsf(th) + sqrtf(fmaf(th, th, 1.0f)));
                    c = rsqrtf(fmaf(t, t, 1.0f));
                    s = t * c;
                    n0 = fmaf(-t, apq, n0);
                    n1 = fmaf( t, apq, n1);
                    any = 1;
                }
                u64 c2 = pk(c, c), s2 = pk(s, s), ns2 = pk(-s, -s);
                #pragma unroll
                for (int j = 0; j < 32; ++j) {
                    u64 x = C0[j];
                    C0[j] = fma2_(c2, x, mul2_(ns2, C1[j]));
                    C1[j] = fma2_(s2, x, mul2_(c2,  C1[j]));
                }
            }
            // ring-shift slot-1 column (and its norm) to the previous lane
            #pragma unroll
            for (int j = 0; j < 32; ++j) C1[j] = __shfl_sync(FULLM, C1[j], lane + 1);
            n1 = __shfl_sync(FULLM, n1, lane + 1);
        }

        if (!__any_sync(FULLM, any)) break;

        // exact norm refresh (kills analytic-carry drift)
        u64 a0 = 0, a1 = 0;
        #pragma unroll
        for (int j = 0; j < 32; ++j) { a0 = fma2_(C0[j], C0[j], a0); a1 = fma2_(C1[j], C1[j], a1); }
        float lo, hi; upk(a0, lo, hi); n0 = lo + hi; upk(a1, lo, hi); n1 = lo + hi;
    }

    // exact norms -> weights w = log(lambda)/lambda^2 = 0.5*log(n)/n
    float e0, e1;
    {
        u64 a0 = 0, a1 = 0;
        #pragma unroll
        for (int j = 0; j < 32; ++j) { a0 = fma2_(C0[j], C0[j], a0); a1 = fma2_(C1[j], C1[j], a1); }
        float lo, hi; upk(a0, lo, hi); e0 = lo + hi; upk(a1, lo, hi); e1 = lo + hi;
    }
    float w0 = 0.5f * logf(fmaxf(e0, 1e-30f)) / e0;
    float w1 = 0.5f * logf(fmaxf(e1, 1e-30f)) / e1;
    u64 w02 = pk(w0, w0), w12 = pk(w1, w1);

    // Store P = columns, Q = w * columns. Layout [b][col][row], rows contiguous.
    u64* Pp = (u64*)(g_P + (size_t)warp * 4096);
    u64* Qp = (u64*)(g_Q + (size_t)warp * 4096);
    #pragma unroll
    for (int j = 0; j < 32; ++j) {
        Pp[lane * 32 + j]        = C0[j];  Qp[lane * 32 + j]        = mul2_(w02, C0[j]);
        Pp[(lane + 32) * 32 + j] = C1[j];  Qp[(lane + 32) * 32 + j] = mul2_(w12, C1[j]);
    }
}

// out[b][i][j] = sum_k P[b][k][i] * Q[b][k][j]
__global__ __launch_bounds__(256) void gram_epilogue(float* __restrict__ out, int B)
{
    __shared__ float Ps[NMAT * NMAT];
    __shared__ float Qs[NMAT * NMAT];
    const int b = blockIdx.x;
    const int tid = threadIdx.x;
    const float* Pb = g_P + (size_t)b * (NMAT * NMAT);
    const float* Qb = g_Q + (size_t)b * (NMAT * NMAT);

    #pragma unroll
    for (int i = tid; i < NMAT * NMAT; i += 256) {
        Ps[i] = Pb[i];
        Qs[i] = Qb[i];
    }
    __syncthreads();

    const int ti = tid >> 6;
    const int tj = tid & 63;
    float acc[16];
    #pragma unroll
    for (int r = 0; r < 16; ++r) acc[r] = 0.0f;

    #pragma unroll 4
    for (int k = 0; k < NMAT; ++k) {
        float qv = Qs[k * NMAT + tj];
        const float4* prow = (const float4*)&Ps[k * NMAT + ti * 16];
        #pragma unroll
        for (int r4 = 0; r4 < 4; ++r4) {
            float4 p = prow[r4];
            acc[4*r4+0] = fmaf(p.x, qv, acc[4*r4+0]);
            acc[4*r4+1] = fmaf(p.y, qv, acc[4*r4+1]);
            acc[4*r4+2] = fmaf(p.z, qv, acc[4*r4+2]);
            acc[4*r4+3] = fmaf(p.w, qv, acc[4*r4+3]);
        }
    }

    float* Ob = out + (size_t)b * (NMAT * NMAT);
    #pragma unroll
    for (int r = 0; r < 16; ++r)
        Ob[(ti * 16 + r) * NMAT + tj] = acc[r];
}

extern "C" void kernel_launch(void* const* d_in, const int* in_sizes, int n_in,
                              void* d_out, int out_size) {
    const float* X = (const float*)d_in[0];
    float* out = (float*)d_out;
    int B = in_sizes[0] / (NMAT * NMAT);
    if (B > MAXB) B = MAXB;
    int blocks = (B + 3) / 4;
    jacobi_xor<<<blocks, 128>>>(X, B);
    gram_epilogue<<<B, 256>>>(out, B);
}